// round 5
// baseline (speedup 1.0000x reference)
#include <cuda_runtime.h>
#include <math.h>

#define H      64
#define NFINE  (1 << 20)          // fine grid intervals over [0,1]
#define NC     (1 << 11)          // coarse grid intervals
#define NCTOT  (NC + 3)           // coarse entries: x = (idx-1)/NC
#define RSH    9                  // log2(NFINE/NC)
#define RMASK  ((1 << RSH) - 1)
#define KBUCK  (1 << 20)          // inverse-index buckets over z in [0,1)
#define MONO   1e-3f

__device__ float g_w2t[H * H];    // g_w2t[i*64+j] = exp(pw2[j][i])  (transposed)
__device__ float g_w1[H], g_b1[H], g_b2[H], g_w3[H], g_b3s;
__device__ float g_Ac[NCTOT];                        // raw A at coarse grid (+/-1 pad)
__device__ __align__(16) float g_T[NFINE + 1];       // normalized F at fine grid
__device__ unsigned long long g_C[KBUCK];            // {J[k] : lo32, T[J[k]+1] : hi32}

__device__ __forceinline__ float sigmoidf(float x) {
    return 1.0f / (1.0f + expf(-x));
}

// ---------------------------------------------------------------------------
// Kernel 0: one-shot weight prep -- exponentiate positivity-constrained
// weights, transpose w2 into global.
// ---------------------------------------------------------------------------
__global__ void prep_kernel(const float* __restrict__ pw1, const float* __restrict__ b1,
                            const float* __restrict__ pw2, const float* __restrict__ b2,
                            const float* __restrict__ pw3, const float* __restrict__ b3) {
    int e = blockIdx.x * blockDim.x + threadIdx.x;
    if (e < H * H) {
        int j = e >> 6, i = e & 63;
        g_w2t[i * H + j] = expf(pw2[e]);
    }
    if (e < H) {
        g_w1[e] = expf(pw1[e]);
        g_b1[e] = b1[e];
        g_b2[e] = b2[e];
        g_w3[e] = expf(pw3[e]);
    }
    if (e == 0) g_b3s = b3[0];
}

// ---------------------------------------------------------------------------
// Kernel 1: exact network eval A(x) on the coarse grid, ONE WARP PER POINT.
// Lane l computes h1[l], h1[l+32]; owns output neurons 2l, 2l+1. h1 broadcast
// via shuffles; w2t read straight from global (coalesced float2 row segments,
// L1-resident across warps).
// ---------------------------------------------------------------------------
__global__ void coarse_kernel() {
    int gwarp = (blockIdx.x * blockDim.x + threadIdx.x) >> 5;
    int lane  = threadIdx.x & 31;
    if (gwarp >= NCTOT) return;
    float x = (float)(gwarp - 1) * (1.0f / (float)NC);

    float h1a = sigmoidf(fmaf(__ldg(&g_w1[lane]),      x, __ldg(&g_b1[lane])));
    float h1b = sigmoidf(fmaf(__ldg(&g_w1[lane + 32]), x, __ldg(&g_b1[lane + 32])));

    float acc0 = __ldg(&g_b2[2 * lane]);
    float acc1 = __ldg(&g_b2[2 * lane + 1]);
#pragma unroll
    for (int i = 0; i < 32; i++) {
        float  hv = __shfl_sync(0xffffffffu, h1a, i);
        float2 w  = __ldg(reinterpret_cast<const float2*>(&g_w2t[i * H + 2 * lane]));
        acc0 = fmaf(w.x, hv, acc0);
        acc1 = fmaf(w.y, hv, acc1);
    }
#pragma unroll
    for (int i = 0; i < 32; i++) {
        float  hv = __shfl_sync(0xffffffffu, h1b, i);
        float2 w  = __ldg(reinterpret_cast<const float2*>(&g_w2t[(i + 32) * H + 2 * lane]));
        acc0 = fmaf(w.x, hv, acc0);
        acc1 = fmaf(w.y, hv, acc1);
    }
    float part = fmaf(sigmoidf(acc0), __ldg(&g_w3[2 * lane]),
                      sigmoidf(acc1) * __ldg(&g_w3[2 * lane + 1]));
#pragma unroll
    for (int o = 16; o; o >>= 1) part += __shfl_xor_sync(0xffffffffu, part, o);

    if (lane == 0) g_Ac[gwarp] = sigmoidf(part + g_b3s) + MONO * x;
}

// ---------------------------------------------------------------------------
// Catmull-Rom interpolation of A at fine index j (error O(h^4), far below
// fp32 rounding of A itself). Coarse points take the exact value.
// ---------------------------------------------------------------------------
__device__ __forceinline__ float evalA(int j) {
    int ci = j >> RSH;
    int f  = j & RMASK;
    if (f == 0) return __ldg(&g_Ac[ci + 1]);
    float t  = (float)f * (1.0f / (float)(1 << RSH));
    float P0 = __ldg(&g_Ac[ci]);
    float P1 = __ldg(&g_Ac[ci + 1]);
    float P2 = __ldg(&g_Ac[ci + 2]);
    float P3 = __ldg(&g_Ac[ci + 3]);
    float c1 = 0.5f * (P2 - P0);
    float c2 = P0 - 2.5f * P1 + 2.0f * P2 - 0.5f * P3;
    float c3 = 1.5f * (P1 - P2) + 0.5f * (P3 - P0);
    return P1 + t * (c1 + t * (c2 + t * c3));
}

// ---------------------------------------------------------------------------
// Kernel 2: fused fine-table + packed inverse index (8B entries, 8 MB total).
// Thread handles 4 fine points j..j+3: evaluates T at j..j+4 (shared
// endpoints use identical arithmetic in every thread, so bucket runs tile
// exactly), float4-stores T, writes g_C[k] = {j, T[j+1]} for
// k in [ceil(T[j]*K), ceil(T[j+1]*K)).
// ---------------------------------------------------------------------------
__global__ void table_kernel() {
    int jb = (blockIdx.x * blockDim.x + threadIdx.x) * 4;
    if (jb >= NFINE) return;
    const float a0      = g_Ac[1];        // A(0)
    const float a1      = g_Ac[1 + NC];   // A(1)
    const float inv_den = 1.0f / (a1 - a0);

    float tv[5];
#pragma unroll
    for (int m = 0; m < 5; m++) {
        int j = jb + m;
        tv[m] = (j == NFINE) ? 1.0f : (evalA(j) - a0) * inv_den;  // j==0 -> exact 0.0f
    }
    *reinterpret_cast<float4*>(&g_T[jb]) = make_float4(tv[0], tv[1], tv[2], tv[3]);
    if (jb + 4 == NFINE) g_T[NFINE] = 1.0f;

#pragma unroll
    for (int m = 0; m < 4; m++) {
        int k0 = (int)ceilf(tv[m]     * (float)KBUCK);   // exact: pow2 scale
        int k1 = (int)ceilf(tv[m + 1] * (float)KBUCK);
        if (k0 < 0) k0 = 0;
        if (k1 > KBUCK) k1 = KBUCK;
        unsigned long long val =
            ((unsigned long long)__float_as_uint(tv[m + 1]) << 32) |
            (unsigned long long)(unsigned)(jb + m);
        for (int k = k0; k < k1; k++) g_C[k] = val;
    }
}

// ---------------------------------------------------------------------------
// Kernel 3: per-target inversion, 8 targets/thread with all 8 bucket gathers
// issued up-front (MLP=8 hides L2 latency). Common path: ONE 8B gather
// (z < T[J+1]). Width-2 path: +C[k+1] (usually same 32B sector), no T loads.
// Wider: bisect on g_T. Equivalent to the reference 20-step bisection.
// ---------------------------------------------------------------------------
__device__ __forceinline__ float resolve(float zi, int k, unsigned long long c0) {
    int   j  = (int)(unsigned)c0;                 // T[j] <= k/K <= zi
    float t1 = __uint_as_float((unsigned)(c0 >> 32));   // T[j+1]
    int lo;
    if (zi < t1) {
        lo = j;
    } else {
        lo = j + 1;                               // T[j+1] <= zi
        int hi = (k < KBUCK - 1)
                   ? ((int)(unsigned)__ldg(&g_C[k + 1]) + 1)
                   : NFINE;                       // T[hi] > zi
        while (hi - lo > 1) {
            int mid = (lo + hi) >> 1;
            if (__ldg(&g_T[mid]) <= zi) lo = mid; else hi = mid;
        }
    }
    return (float)(2 * lo + 1) * 0x1p-21f;        // (lo + hi)/2 * 2^-20, exact
}

__global__ void search_kernel(const float* __restrict__ z, float* __restrict__ out, int n) {
    int i = (blockIdx.x * blockDim.x + threadIdx.x) * 8;
    if (i + 7 < n) {
        float4 za = *reinterpret_cast<const float4*>(z + i);
        float4 zb = *reinterpret_cast<const float4*>(z + i + 4);
        float zv[8] = {za.x, za.y, za.z, za.w, zb.x, zb.y, zb.z, zb.w};
        int k[8];
        unsigned long long c[8];
#pragma unroll
        for (int m = 0; m < 8; m++) {
            k[m] = (int)(zv[m] * (float)KBUCK);   // exact floor: pow2 scale
            k[m] = min(max(k[m], 0), KBUCK - 1);
        }
#pragma unroll
        for (int m = 0; m < 8; m++) c[m] = __ldg(&g_C[k[m]]);   // 8 independent gathers
        float ov[8];
#pragma unroll
        for (int m = 0; m < 8; m++) ov[m] = resolve(zv[m], k[m], c[m]);
        *reinterpret_cast<float4*>(out + i)     = make_float4(ov[0], ov[1], ov[2], ov[3]);
        *reinterpret_cast<float4*>(out + i + 4) = make_float4(ov[4], ov[5], ov[6], ov[7]);
    } else {
        for (; i < n; i++) {
            float zi = z[i];
            int k = (int)(zi * (float)KBUCK);
            k = min(max(k, 0), KBUCK - 1);
            out[i] = resolve(zi, k, __ldg(&g_C[k]));
        }
    }
}

// ---------------------------------------------------------------------------
extern "C" void kernel_launch(void* const* d_in, const int* in_sizes, int n_in,
                              void* d_out, int out_size) {
    const float* z   = (const float*)d_in[0];
    const float* pw1 = (const float*)d_in[1];
    const float* b1  = (const float*)d_in[2];
    const float* pw2 = (const float*)d_in[3];
    const float* b2  = (const float*)d_in[4];
    const float* pw3 = (const float*)d_in[5];
    const float* b3  = (const float*)d_in[6];
    float* out = (float*)d_out;
    int n = in_sizes[0];

    prep_kernel<<<(H * H + 255) / 256, 256>>>(pw1, b1, pw2, b2, pw3, b3);
    coarse_kernel<<<(NCTOT * 32 + 255) / 256, 256>>>();
    table_kernel<<<(NFINE / 4 + 255) / 256, 256>>>();
    int nt = (n + 7) / 8;
    search_kernel<<<(nt + 255) / 256, 256>>>(z, out, n);
}

// round 6
// speedup vs baseline: 1.1603x; 1.1603x over previous
#include <cuda_runtime.h>
#include <math.h>

#define H      64
#define NFINE  (1 << 20)          // fine grid intervals over [0,1]
#define NC     (1 << 11)          // coarse grid intervals
#define NCTOT  (NC + 3)           // coarse entries: x = (idx-1)/NC
#define RSH    9                  // log2(NFINE/NC)
#define RMASK  ((1 << RSH) - 1)
#define KBUCK  (1 << 19)          // inverse-index buckets (8 MB of 16B entries)
#define MONO   1e-3f

__device__ float g_w2t[H * H];    // g_w2t[i*64+j] = exp(pw2[j][i])  (transposed)
__device__ float g_w1[H], g_b1[H], g_b2[H], g_w3[H], g_b3s;
__device__ float g_Ac[NCTOT];                        // raw A at coarse grid (+/-1 pad)
__device__ __align__(16) float g_T[NFINE + 1];       // normalized F at fine grid
__device__ uint4 g_C[KBUCK];      // {J[k], T[J+1], T[J+2], T[J+3]} (floats as bits)

__device__ __forceinline__ float sigmoidf(float x) {
    return 1.0f / (1.0f + expf(-x));
}

// ---------------------------------------------------------------------------
// Kernel 0: one-shot weight prep -- exponentiate positivity-constrained
// weights, transpose w2 into global.
// ---------------------------------------------------------------------------
__global__ void prep_kernel(const float* __restrict__ pw1, const float* __restrict__ b1,
                            const float* __restrict__ pw2, const float* __restrict__ b2,
                            const float* __restrict__ pw3, const float* __restrict__ b3) {
    int e = blockIdx.x * blockDim.x + threadIdx.x;
    if (e < H * H) {
        int j = e >> 6, i = e & 63;
        g_w2t[i * H + j] = expf(pw2[e]);
    }
    if (e < H) {
        g_w1[e] = expf(pw1[e]);
        g_b1[e] = b1[e];
        g_b2[e] = b2[e];
        g_w3[e] = expf(pw3[e]);
    }
    if (e == 0) g_b3s = b3[0];
}

// ---------------------------------------------------------------------------
// Kernel 1: exact network eval A(x) on the coarse grid, ONE WARP PER POINT.
// ---------------------------------------------------------------------------
__global__ void coarse_kernel() {
    int gwarp = (blockIdx.x * blockDim.x + threadIdx.x) >> 5;
    int lane  = threadIdx.x & 31;
    if (gwarp >= NCTOT) return;
    float x = (float)(gwarp - 1) * (1.0f / (float)NC);

    float h1a = sigmoidf(fmaf(__ldg(&g_w1[lane]),      x, __ldg(&g_b1[lane])));
    float h1b = sigmoidf(fmaf(__ldg(&g_w1[lane + 32]), x, __ldg(&g_b1[lane + 32])));

    float acc0 = __ldg(&g_b2[2 * lane]);
    float acc1 = __ldg(&g_b2[2 * lane + 1]);
#pragma unroll
    for (int i = 0; i < 32; i++) {
        float  hv = __shfl_sync(0xffffffffu, h1a, i);
        float2 w  = __ldg(reinterpret_cast<const float2*>(&g_w2t[i * H + 2 * lane]));
        acc0 = fmaf(w.x, hv, acc0);
        acc1 = fmaf(w.y, hv, acc1);
    }
#pragma unroll
    for (int i = 0; i < 32; i++) {
        float  hv = __shfl_sync(0xffffffffu, h1b, i);
        float2 w  = __ldg(reinterpret_cast<const float2*>(&g_w2t[(i + 32) * H + 2 * lane]));
        acc0 = fmaf(w.x, hv, acc0);
        acc1 = fmaf(w.y, hv, acc1);
    }
    float part = fmaf(sigmoidf(acc0), __ldg(&g_w3[2 * lane]),
                      sigmoidf(acc1) * __ldg(&g_w3[2 * lane + 1]));
#pragma unroll
    for (int o = 16; o; o >>= 1) part += __shfl_xor_sync(0xffffffffu, part, o);

    if (lane == 0) g_Ac[gwarp] = sigmoidf(part + g_b3s) + MONO * x;
}

// ---------------------------------------------------------------------------
// Catmull-Rom interpolation of A at fine index j (error O(h^4), far below
// fp32 rounding of A itself). Coarse points take the exact value.
// ---------------------------------------------------------------------------
__device__ __forceinline__ float evalA(int j) {
    int ci = j >> RSH;
    int f  = j & RMASK;
    if (f == 0) return __ldg(&g_Ac[ci + 1]);
    float t  = (float)f * (1.0f / (float)(1 << RSH));
    float P0 = __ldg(&g_Ac[ci]);
    float P1 = __ldg(&g_Ac[ci + 1]);
    float P2 = __ldg(&g_Ac[ci + 2]);
    float P3 = __ldg(&g_Ac[ci + 3]);
    float c1 = 0.5f * (P2 - P0);
    float c2 = P0 - 2.5f * P1 + 2.0f * P2 - 0.5f * P3;
    float c3 = 1.5f * (P1 - P2) + 0.5f * (P3 - P0);
    return P1 + t * (c1 + t * (c2 + t * c3));
}

// ---------------------------------------------------------------------------
// Kernel 2: fused fine-table + fat packed inverse index (16B entries at
// KBUCK=2^19 -> 8 MB, L2-resident). Thread handles 4 fine points j..j+3:
// evaluates T at j..j+6 (shared endpoints use identical arithmetic in every
// thread, so bucket runs tile exactly), float4-stores T, and writes
// g_C[k] = {j, T[j+1], T[j+2], T[j+3]} for k in [ceil(T[j]*K), ceil(T[j+1]*K)).
// ---------------------------------------------------------------------------
__global__ void table_kernel() {
    int jb = (blockIdx.x * blockDim.x + threadIdx.x) * 4;
    if (jb >= NFINE) return;
    const float a0      = g_Ac[1];        // A(0)
    const float a1      = g_Ac[1 + NC];   // A(1)
    const float inv_den = 1.0f / (a1 - a0);

    float tv[7];
#pragma unroll
    for (int m = 0; m < 7; m++) {
        int j = jb + m;
        if (j < NFINE)       tv[m] = (evalA(j) - a0) * inv_den;  // j==0 -> exact 0.0f
        else if (j == NFINE) tv[m] = 1.0f;
        else                 tv[m] = 2.0f;                       // sentinel > any z
    }
    *reinterpret_cast<float4*>(&g_T[jb]) = make_float4(tv[0], tv[1], tv[2], tv[3]);
    if (jb + 4 == NFINE) g_T[NFINE] = 1.0f;

#pragma unroll
    for (int m = 0; m < 4; m++) {
        int k0 = (int)ceilf(tv[m]     * (float)KBUCK);   // exact: pow2 scale
        int k1 = (int)ceilf(fminf(tv[m + 1], 1.0f) * (float)KBUCK);
        if (k0 < 0) k0 = 0;
        if (k1 > KBUCK) k1 = KBUCK;
        uint4 val = make_uint4((unsigned)(jb + m),
                               __float_as_uint(tv[m + 1]),
                               __float_as_uint(tv[m + 2]),
                               __float_as_uint(tv[m + 3]));
        for (int k = k0; k < k1; k++) g_C[k] = val;
    }
}

// ---------------------------------------------------------------------------
// Kernel 3: per-target inversion, 4 targets/thread, all 4 bucket gathers
// issued before any resolution. ONE aligned 16B gather (single 32B sector)
// resolves bracket widths <= 3 (dominant at 2 avg points/bucket); wider
// brackets load C[k+1].x and bisect on g_T. Equivalent to the reference
// 20-step bisection: lo = max{j : T[j] <= z}, out = (lo+0.5)*2^-20.
// ---------------------------------------------------------------------------
__device__ __forceinline__ float resolve(float zi, int k, uint4 c) {
    int   j  = (int)c.x;                          // T[j] <= k/K <= zi
    float t1 = __uint_as_float(c.y);
    float t2 = __uint_as_float(c.z);
    float t3 = __uint_as_float(c.w);
    int lo;
    if (zi < t1)      lo = j;
    else if (zi < t2) lo = j + 1;
    else if (zi < t3) lo = j + 2;
    else {
        lo = j + 3;                               // T[j+3] <= zi
        int hi = (k < KBUCK - 1)
                   ? ((int)__ldg(reinterpret_cast<const unsigned*>(&g_C[k + 1])) + 1)
                   : NFINE;                       // T[hi] > zi
        while (hi - lo > 1) {
            int mid = (lo + hi) >> 1;
            if (__ldg(&g_T[mid]) <= zi) lo = mid; else hi = mid;
        }
    }
    return (float)(2 * lo + 1) * 0x1p-21f;        // (lo + hi)/2 * 2^-20, exact
}

__global__ void search_kernel(const float* __restrict__ z, float* __restrict__ out, int n) {
    int i = (blockIdx.x * blockDim.x + threadIdx.x) * 4;
    if (i + 3 < n) {
        float4 zv = *reinterpret_cast<const float4*>(z + i);
        float zr[4] = {zv.x, zv.y, zv.z, zv.w};
        int k[4];
        uint4 c[4];
#pragma unroll
        for (int m = 0; m < 4; m++) {
            k[m] = (int)(zr[m] * (float)KBUCK);   // exact floor: pow2 scale
            k[m] = min(max(k[m], 0), KBUCK - 1);
        }
#pragma unroll
        for (int m = 0; m < 4; m++) c[m] = __ldg(&g_C[k[m]]);   // 4 independent gathers
        float4 ov;
        ov.x = resolve(zr[0], k[0], c[0]);
        ov.y = resolve(zr[1], k[1], c[1]);
        ov.z = resolve(zr[2], k[2], c[2]);
        ov.w = resolve(zr[3], k[3], c[3]);
        *reinterpret_cast<float4*>(out + i) = ov;
    } else {
        for (; i < n; i++) {
            float zi = z[i];
            int k = (int)(zi * (float)KBUCK);
            k = min(max(k, 0), KBUCK - 1);
            out[i] = resolve(zi, k, __ldg(&g_C[k]));
        }
    }
}

// ---------------------------------------------------------------------------
extern "C" void kernel_launch(void* const* d_in, const int* in_sizes, int n_in,
                              void* d_out, int out_size) {
    const float* z   = (const float*)d_in[0];
    const float* pw1 = (const float*)d_in[1];
    const float* b1  = (const float*)d_in[2];
    const float* pw2 = (const float*)d_in[3];
    const float* b2  = (const float*)d_in[4];
    const float* pw3 = (const float*)d_in[5];
    const float* b3  = (const float*)d_in[6];
    float* out = (float*)d_out;
    int n = in_sizes[0];

    prep_kernel<<<(H * H + 255) / 256, 256>>>(pw1, b1, pw2, b2, pw3, b3);
    coarse_kernel<<<(NCTOT * 32 + 255) / 256, 256>>>();
    table_kernel<<<(NFINE / 4 + 255) / 256, 256>>>();
    int nq = (n + 3) / 4;
    search_kernel<<<(nq + 255) / 256, 256>>>(z, out, n);
}

// round 7
// speedup vs baseline: 1.2772x; 1.1007x over previous
#include <cuda_runtime.h>
#include <math.h>

#define H      64
#define NFINE  (1 << 20)          // fine grid intervals over [0,1]
#define NC     (1 << 11)          // coarse grid intervals
#define NCTOT  (NC + 3)           // coarse entries: x = (idx-1)/NC
#define RSH    9                  // log2(NFINE/NC)
#define RMASK  ((1 << RSH) - 1)
#define KBUCK  (1 << 19)          // inverse-index buckets (8 MB of 16B entries)
#define MONO   1e-3f

__device__ float g_w2t[H * H];    // g_w2t[i*64+j] = exp(pw2[j][i])  (transposed)
__device__ float g_w1[H], g_b1[H], g_b2[H], g_w3[H], g_b3s;
__device__ float g_Ac[NCTOT];                        // raw A at coarse grid (+/-1 pad)
__device__ __align__(16) float g_T[NFINE + 1];       // normalized F at fine grid
__device__ uint4 g_C[KBUCK];      // {J[k], T[J+1], T[J+2], T[J+3]} (floats as bits)

__device__ __forceinline__ float sigmoidf(float x) {
    return 1.0f / (1.0f + expf(-x));
}

// ---------------------------------------------------------------------------
// Kernel 0: one-shot weight prep -- exponentiate positivity-constrained
// weights, transpose w2 into global.
// ---------------------------------------------------------------------------
__global__ void prep_kernel(const float* __restrict__ pw1, const float* __restrict__ b1,
                            const float* __restrict__ pw2, const float* __restrict__ b2,
                            const float* __restrict__ pw3, const float* __restrict__ b3) {
    int e = blockIdx.x * blockDim.x + threadIdx.x;
    if (e < H * H) {
        int j = e >> 6, i = e & 63;
        g_w2t[i * H + j] = expf(pw2[e]);
    }
    if (e < H) {
        g_w1[e] = expf(pw1[e]);
        g_b1[e] = b1[e];
        g_b2[e] = b2[e];
        g_w3[e] = expf(pw3[e]);
    }
    if (e == 0) g_b3s = b3[0];
}

// ---------------------------------------------------------------------------
// Kernel 1: exact network eval A(x) on the coarse grid, ONE WARP PER POINT.
// ---------------------------------------------------------------------------
__global__ void coarse_kernel() {
    int gwarp = (blockIdx.x * blockDim.x + threadIdx.x) >> 5;
    int lane  = threadIdx.x & 31;
    if (gwarp >= NCTOT) return;
    float x = (float)(gwarp - 1) * (1.0f / (float)NC);

    float h1a = sigmoidf(fmaf(__ldg(&g_w1[lane]),      x, __ldg(&g_b1[lane])));
    float h1b = sigmoidf(fmaf(__ldg(&g_w1[lane + 32]), x, __ldg(&g_b1[lane + 32])));

    float acc0 = __ldg(&g_b2[2 * lane]);
    float acc1 = __ldg(&g_b2[2 * lane + 1]);
#pragma unroll
    for (int i = 0; i < 32; i++) {
        float  hv = __shfl_sync(0xffffffffu, h1a, i);
        float2 w  = __ldg(reinterpret_cast<const float2*>(&g_w2t[i * H + 2 * lane]));
        acc0 = fmaf(w.x, hv, acc0);
        acc1 = fmaf(w.y, hv, acc1);
    }
#pragma unroll
    for (int i = 0; i < 32; i++) {
        float  hv = __shfl_sync(0xffffffffu, h1b, i);
        float2 w  = __ldg(reinterpret_cast<const float2*>(&g_w2t[(i + 32) * H + 2 * lane]));
        acc0 = fmaf(w.x, hv, acc0);
        acc1 = fmaf(w.y, hv, acc1);
    }
    float part = fmaf(sigmoidf(acc0), __ldg(&g_w3[2 * lane]),
                      sigmoidf(acc1) * __ldg(&g_w3[2 * lane + 1]));
#pragma unroll
    for (int o = 16; o; o >>= 1) part += __shfl_xor_sync(0xffffffffu, part, o);

    if (lane == 0) g_Ac[gwarp] = sigmoidf(part + g_b3s) + MONO * x;
}

// ---------------------------------------------------------------------------
// Catmull-Rom interpolation of A at fine index j (error O(h^4), far below
// fp32 rounding of A itself). Coarse points take the exact value.
// ---------------------------------------------------------------------------
__device__ __forceinline__ float evalA(int j) {
    int ci = j >> RSH;
    int f  = j & RMASK;
    if (f == 0) return __ldg(&g_Ac[ci + 1]);
    float t  = (float)f * (1.0f / (float)(1 << RSH));
    float P0 = __ldg(&g_Ac[ci]);
    float P1 = __ldg(&g_Ac[ci + 1]);
    float P2 = __ldg(&g_Ac[ci + 2]);
    float P3 = __ldg(&g_Ac[ci + 3]);
    float c1 = 0.5f * (P2 - P0);
    float c2 = P0 - 2.5f * P1 + 2.0f * P2 - 0.5f * P3;
    float c3 = 1.5f * (P1 - P2) + 0.5f * (P3 - P0);
    return P1 + t * (c1 + t * (c2 + t * c3));
}

// ---------------------------------------------------------------------------
// Kernel 2: fused fine-table + fat packed inverse index (16B entries at
// KBUCK=2^19 -> 8 MB, L2-resident). Thread handles 4 fine points j..j+3:
// evaluates T at j..j+6 (shared endpoints use identical arithmetic in every
// thread, so bucket runs tile exactly), float4-stores T, and writes
// g_C[k] = {j, T[j+1], T[j+2], T[j+3]} for k in [ceil(T[j]*K), ceil(T[j+1]*K)).
// ---------------------------------------------------------------------------
__global__ void table_kernel() {
    int jb = (blockIdx.x * blockDim.x + threadIdx.x) * 4;
    if (jb >= NFINE) return;
    const float a0      = g_Ac[1];        // A(0)
    const float a1      = g_Ac[1 + NC];   // A(1)
    const float inv_den = 1.0f / (a1 - a0);

    float tv[7];
#pragma unroll
    for (int m = 0; m < 7; m++) {
        int j = jb + m;
        if (j < NFINE)       tv[m] = (evalA(j) - a0) * inv_den;  // j==0 -> exact 0.0f
        else if (j == NFINE) tv[m] = 1.0f;
        else                 tv[m] = 2.0f;                       // sentinel > any z
    }
    *reinterpret_cast<float4*>(&g_T[jb]) = make_float4(tv[0], tv[1], tv[2], tv[3]);
    if (jb + 4 == NFINE) g_T[NFINE] = 1.0f;

#pragma unroll
    for (int m = 0; m < 4; m++) {
        int k0 = (int)ceilf(tv[m]     * (float)KBUCK);   // exact: pow2 scale
        int k1 = (int)ceilf(fminf(tv[m + 1], 1.0f) * (float)KBUCK);
        if (k0 < 0) k0 = 0;
        if (k1 > KBUCK) k1 = KBUCK;
        uint4 val = make_uint4((unsigned)(jb + m),
                               __float_as_uint(tv[m + 1]),
                               __float_as_uint(tv[m + 2]),
                               __float_as_uint(tv[m + 3]));
        for (int k = k0; k < k1; k++) g_C[k] = val;
    }
}

// ---------------------------------------------------------------------------
// Kernel 3: per-target inversion, 4 targets/thread, SEQUENTIAL low-register
// form (R4 structure: 19 regs, occ ~77% -- the HW scoreboards already keep
// the four independent chains in flight; explicit batching only burns regs).
// ONE aligned 16B gather (single 32B sector) resolves bracket widths <= 3
// (dominant at 2 avg points/bucket); wider brackets load C[k+1].x and bisect
// on g_T. Equivalent to the reference 20-step bisection:
// lo = max{j : T[j] <= z}, out = (lo+0.5)*2^-20.
// ---------------------------------------------------------------------------
__device__ __forceinline__ float invert_one(float zi) {
    int k = (int)(zi * (float)KBUCK);            // exact floor: pow2 scale
    k = min(max(k, 0), KBUCK - 1);
    uint4 c = __ldg(&g_C[k]);
    int   j  = (int)c.x;                         // T[j] <= k/K <= zi
    float t1 = __uint_as_float(c.y);
    float t2 = __uint_as_float(c.z);
    float t3 = __uint_as_float(c.w);
    int lo;
    if (zi < t1)      lo = j;
    else if (zi < t2) lo = j + 1;
    else if (zi < t3) lo = j + 2;
    else {
        lo = j + 3;                              // T[j+3] <= zi
        int hi = (k < KBUCK - 1)
                   ? ((int)__ldg(reinterpret_cast<const unsigned*>(&g_C[k + 1])) + 1)
                   : NFINE;                      // T[hi] > zi
        while (hi - lo > 1) {
            int mid = (lo + hi) >> 1;
            if (__ldg(&g_T[mid]) <= zi) lo = mid; else hi = mid;
        }
    }
    return (float)(2 * lo + 1) * 0x1p-21f;       // (lo + hi)/2 * 2^-20, exact
}

__global__ void search_kernel(const float* __restrict__ z, float* __restrict__ out, int n) {
    int i = (blockIdx.x * blockDim.x + threadIdx.x) * 4;
    if (i + 3 < n) {
        float4 zv = *reinterpret_cast<const float4*>(z + i);
        float4 ov;
        ov.x = invert_one(zv.x);
        ov.y = invert_one(zv.y);
        ov.z = invert_one(zv.z);
        ov.w = invert_one(zv.w);
        *reinterpret_cast<float4*>(out + i) = ov;
    } else {
        for (; i < n; i++) out[i] = invert_one(z[i]);
    }
}

// ---------------------------------------------------------------------------
extern "C" void kernel_launch(void* const* d_in, const int* in_sizes, int n_in,
                              void* d_out, int out_size) {
    const float* z   = (const float*)d_in[0];
    const float* pw1 = (const float*)d_in[1];
    const float* b1  = (const float*)d_in[2];
    const float* pw2 = (const float*)d_in[3];
    const float* b2  = (const float*)d_in[4];
    const float* pw3 = (const float*)d_in[5];
    const float* b3  = (const float*)d_in[6];
    float* out = (float*)d_out;
    int n = in_sizes[0];

    prep_kernel<<<(H * H + 255) / 256, 256>>>(pw1, b1, pw2, b2, pw3, b3);
    coarse_kernel<<<(NCTOT * 32 + 255) / 256, 256>>>();
    table_kernel<<<(NFINE / 4 + 255) / 256, 256>>>();
    int nq = (n + 3) / 4;
    search_kernel<<<(nq + 255) / 256, 256>>>(z, out, n);
}